// round 6
// baseline (speedup 1.0000x reference)
#include <cuda_runtime.h>

// NeuralODETorch: 131072 independent 4-dim states, MLP field 4->32(softplus)->4(tanh).
// RK4 fixed step: 3 steps of h = t1/3, each covering 33 save-intervals.
// Cubic-Hermite dense output, 32 interior points per step collapsed:
//   sum_{k=1..32} H(k/33) = 16*(y+yn) + (272/99)*h*(f - fn).
// This version processes 2 batch elements per thread with packed f32x2 math
// (fma.rn.f32x2); weights live in shared memory pre-duplicated {w,w} so one
// LDS.64 yields the packed broadcast. MUFU (ex2/lg2/rcp) stays scalar per lane.

#define HID 32
#define NSTEP 3
#define TPB 64
#define MAXBLOCKS 1024

typedef unsigned long long u64;

static __device__ float g_partials[MAXBLOCKS];
static __device__ int   g_count = 0;

struct WP {
    u64 w1x[HID], w1y[HID], w1z[HID], w1w[HID], b1[HID];  // pre-scaled by log2e, duplicated
    u64 w2a[HID], w2b[HID], w2c[HID], w2d[HID];           // W2^T cols, pre-scaled by ln2, duplicated
    float b2[4];
    float t1;
};

// ---- f32x2 helpers ----
__device__ __forceinline__ u64 pk2(float a, float b) {
    u64 r; asm("mov.b64 %0, {%1, %2};" : "=l"(r) : "f"(a), "f"(b)); return r;
}
__device__ __forceinline__ void up2(u64 v, float& a, float& b) {
    asm("mov.b64 {%0, %1}, %2;" : "=f"(a), "=f"(b) : "l"(v));
}
__device__ __forceinline__ u64 fma2(u64 a, u64 b, u64 c) {
    u64 d; asm("fma.rn.f32x2 %0, %1, %2, %3;" : "=l"(d) : "l"(a), "l"(b), "l"(c)); return d;
}
__device__ __forceinline__ u64 add2(u64 a, u64 b) {
    u64 d; asm("add.rn.f32x2 %0, %1, %2;" : "=l"(d) : "l"(a), "l"(b)); return d;
}
__device__ __forceinline__ u64 neg2(u64 a) { return a ^ 0x8000000080000000ULL; }

struct P4 { u64 x, y, z, w; };

// ---- scalar MUFU helpers ----
__device__ __forceinline__ float ex2f(float x) {
    float y; asm("ex2.approx.f32 %0, %1;" : "=f"(y) : "f"(x)); return y;
}
__device__ __forceinline__ float lg2f(float x) {
    float y; asm("lg2.approx.f32 %0, %1;" : "=f"(y) : "f"(x)); return y;
}
__device__ __forceinline__ float rcpf(float x) {
    float y; asm("rcp.approx.f32 %0, %1;" : "=f"(y) : "f"(x)); return y;
}
__device__ __forceinline__ float tanh_f(float x) {
    const float c = -2.8853900817779268f;  // -2*log2(e)
    float t = ex2f(c * fabsf(x));
    float r = (1.0f - t) * rcpf(1.0f + t);
    return copysignf(r, x);
}
__device__ __forceinline__ float sp_f(float x) {     // softplus(x)/ln2, x pre-scaled by log2e
    return lg2f(1.0f + ex2f(x));
}

// Packed vector field: 2 elements at once, layer-2 fused.
__device__ __forceinline__ P4 vf(const WP& s, P4 Y) {
    u64 A0 = pk2(s.b2[0], s.b2[0]);
    u64 A1 = pk2(s.b2[1], s.b2[1]);
    u64 A2 = pk2(s.b2[2], s.b2[2]);
    u64 A3 = pk2(s.b2[3], s.b2[3]);
#pragma unroll
    for (int j = 0; j < HID; j++) {
        u64 x2 = s.b1[j];
        x2 = fma2(s.w1x[j], Y.x, x2);
        x2 = fma2(s.w1y[j], Y.y, x2);
        x2 = fma2(s.w1z[j], Y.z, x2);
        x2 = fma2(s.w1w[j], Y.w, x2);
        float xa, xb; up2(x2, xa, xb);
        u64 h2 = pk2(sp_f(xa), sp_f(xb));
        A0 = fma2(s.w2a[j], h2, A0);
        A1 = fma2(s.w2b[j], h2, A1);
        A2 = fma2(s.w2c[j], h2, A2);
        A3 = fma2(s.w2d[j], h2, A3);
    }
    float a, b;
    P4 F;
    up2(A0, a, b); F.x = pk2(tanh_f(a), tanh_f(b));
    up2(A1, a, b); F.y = pk2(tanh_f(a), tanh_f(b));
    up2(A2, a, b); F.z = pk2(tanh_f(a), tanh_f(b));
    up2(A3, a, b); F.w = pk2(tanh_f(a), tanh_f(b));
    return F;
}

__device__ __forceinline__ u64 sum4(P4 v) {
    return add2(add2(v.x, v.y), add2(v.z, v.w));
}

__global__ void __launch_bounds__(TPB, 8) ode_kernel(
    const float4* __restrict__ y0,
    const float*  __restrict__ W1,
    const float*  __restrict__ b1,
    const float*  __restrict__ W2,
    const float*  __restrict__ b2,
    const float*  __restrict__ t1p,
    float* __restrict__ out,
    int B)
{
    __shared__ WP s;
    __shared__ float warp_sums[TPB / 32];

    const float LOG2E = 1.4426950408889634f;
    const float LN2   = 0.6931471805599453f;

    int tid = threadIdx.x;
    if (tid < HID) {
        float4 w = reinterpret_cast<const float4*>(W1)[tid];
        s.w1x[tid] = pk2(w.x * LOG2E, w.x * LOG2E);
        s.w1y[tid] = pk2(w.y * LOG2E, w.y * LOG2E);
        s.w1z[tid] = pk2(w.z * LOG2E, w.z * LOG2E);
        s.w1w[tid] = pk2(w.w * LOG2E, w.w * LOG2E);
        float bb = b1[tid] * LOG2E;
        s.b1[tid] = pk2(bb, bb);
        float c0 = W2[0 * HID + tid] * LN2;
        float c1 = W2[1 * HID + tid] * LN2;
        float c2 = W2[2 * HID + tid] * LN2;
        float c3 = W2[3 * HID + tid] * LN2;
        s.w2a[tid] = pk2(c0, c0);
        s.w2b[tid] = pk2(c1, c1);
        s.w2c[tid] = pk2(c2, c2);
        s.w2d[tid] = pk2(c3, c3);
    }
    if (tid < 4) s.b2[tid] = b2[tid];
    if (tid == 0) s.t1 = t1p[0];
    __syncthreads();

    int pidx = blockIdx.x * TPB + tid;   // pair index
    int i0 = 2 * pidx;
    float ssum = 0.0f;

    if (i0 < B) {
        int i1 = (i0 + 1 < B) ? (i0 + 1) : i0;   // clamp; lane b masked below
        bool b_valid = (i0 + 1 < B);

        float4 ya = y0[i0];
        float4 yb = y0[i1];
        P4 Y;
        Y.x = pk2(ya.x, yb.x);
        Y.y = pk2(ya.y, yb.y);
        Y.z = pk2(ya.z, yb.z);
        Y.w = pk2(ya.w, yb.w);

        const float dt  = s.t1 * (1.0f / 3.0f);
        const float hdt = 0.5f * dt;
        const float c6  = dt * (1.0f / 6.0f);
        const float ch  = dt * (272.0f / 99.0f);
        const u64 HDT = pk2(hdt, hdt);
        const u64 DT  = pk2(dt, dt);
        const u64 C6  = pk2(c6, c6);
        const u64 CH  = pk2(ch, ch);
        const u64 C2  = pk2(2.0f, 2.0f);
        const u64 C16 = pk2(16.0f, 16.0f);
        const u64 C17 = pk2(17.0f, 17.0f);

        u64 S = sum4(Y);                 // save at t=0 (both lanes)
        P4 f = vf(s, Y);                 // k1 of first step

#pragma unroll 1
        for (int st = 0; st < NSTEP; st++) {
            P4 k1 = f;
            P4 yt;
            yt.x = fma2(HDT, k1.x, Y.x);
            yt.y = fma2(HDT, k1.y, Y.y);
            yt.z = fma2(HDT, k1.z, Y.z);
            yt.w = fma2(HDT, k1.w, Y.w);
            P4 k2 = vf(s, yt);
            yt.x = fma2(HDT, k2.x, Y.x);
            yt.y = fma2(HDT, k2.y, Y.y);
            yt.z = fma2(HDT, k2.z, Y.z);
            yt.w = fma2(HDT, k2.w, Y.w);
            P4 k3 = vf(s, yt);
            yt.x = fma2(DT, k3.x, Y.x);
            yt.y = fma2(DT, k3.y, Y.y);
            yt.z = fma2(DT, k3.z, Y.z);
            yt.w = fma2(DT, k3.w, Y.w);
            P4 k4 = vf(s, yt);

            P4 yn;
            yn.x = fma2(C6, fma2(C2, add2(k2.x, k3.x), add2(k1.x, k4.x)), Y.x);
            yn.y = fma2(C6, fma2(C2, add2(k2.y, k3.y), add2(k1.y, k4.y)), Y.y);
            yn.z = fma2(C6, fma2(C2, add2(k2.z, k3.z), add2(k1.z, k4.z)), Y.z);
            yn.w = fma2(C6, fma2(C2, add2(k2.w, k3.w), add2(k1.w, k4.w)), Y.w);

            P4 fn = vf(s, yn);

            // 32 interior Hermite samples + endpoint save:
            //   16*(y+yn) + yn + (272/99)*h*(f-fn)
            u64 sy  = sum4(Y);
            u64 syn = sum4(yn);
            u64 sd  = add2(sum4(f), neg2(sum4(fn)));
            S = fma2(C16, sy, S);
            S = fma2(C17, syn, S);
            S = fma2(CH, sd, S);

            Y = yn;
            f = fn;
        }

        float sa, sb; up2(S, sa, sb);
        ssum = sa + (b_valid ? sb : 0.0f);
    }

    // Block reduction -> per-block partial
#pragma unroll
    for (int o = 16; o > 0; o >>= 1)
        ssum += __shfl_xor_sync(0xFFFFFFFFu, ssum, o);
    int lane = tid & 31;
    int wid  = tid >> 5;
    if (lane == 0) warp_sums[wid] = ssum;
    __syncthreads();

    __shared__ bool is_last;
    if (tid == 0) {
        float bs = 0.0f;
#pragma unroll
        for (int w = 0; w < TPB / 32; w++) bs += warp_sums[w];
        g_partials[blockIdx.x] = bs;
        __threadfence();
        int prev = atomicAdd(&g_count, 1);
        is_last = (prev == gridDim.x - 1);
    }
    __syncthreads();

    // Last block: reduce all partials in double, write scalar, reset counter.
    if (is_last) {
        double acc = 0.0;
        for (int i = tid; i < gridDim.x; i += TPB)
            acc += (double)g_partials[i];
#pragma unroll
        for (int o = 16; o > 0; o >>= 1)
            acc += __shfl_xor_sync(0xFFFFFFFFu, acc, o);
        __shared__ double wsd[TPB / 32];
        if (lane == 0) wsd[wid] = acc;
        __syncthreads();
        if (tid == 0) {
            double tot = 0.0;
#pragma unroll
            for (int w = 0; w < TPB / 32; w++) tot += wsd[w];
            out[0] = (float)tot;
            g_count = 0;   // self-reset for next graph replay
        }
    }
}

extern "C" void kernel_launch(void* const* d_in, const int* in_sizes, int n_in,
                              void* d_out, int out_size) {
    const float* y0 = (const float*)d_in[0];
    const float* W1 = (const float*)d_in[1];
    const float* b1 = (const float*)d_in[2];
    const float* W2 = (const float*)d_in[3];
    const float* b2 = (const float*)d_in[4];
    const float* t1 = (const float*)d_in[5];
    float* out = (float*)d_out;

    int B = in_sizes[0] / 4;
    int pairs = (B + 1) / 2;                   // 65536
    int blocks = (pairs + TPB - 1) / TPB;      // 1024

    ode_kernel<<<blocks, TPB>>>(reinterpret_cast<const float4*>(y0),
                                W1, b1, W2, b2, t1, out, B);
}

// round 7
// speedup vs baseline: 1.1745x; 1.1745x over previous
#include <cuda_runtime.h>

// NeuralODETorch: 131072 independent 4-dim states, MLP field 4->32(softplus)->4(tanh).
// RK4 fixed step: 3 steps of h = t1/3, each covering 33 save-intervals.
// Cubic-Hermite dense output, 32 interior points per step collapsed:
//   sum_{k=1..32} H(k/33) = 16*(y+yn) + (272/99)*h*(f - fn).
// 2 batch elements per thread with packed f32x2 math (FFMA2); weights in shared
// pre-duplicated {w,w}. RK4 in accumulate form (k2/k3 never co-live) and f kept
// only as its component-sum, so the live set fits a 128-register cap (16 warps/SM).

#define HID 32
#define NSTEP 3
#define TPB 64
#define MAXBLOCKS 1024

typedef unsigned long long u64;

static __device__ float g_partials[MAXBLOCKS];
static __device__ int   g_count = 0;

struct WP {
    u64 w1x[HID], w1y[HID], w1z[HID], w1w[HID], b1[HID];  // pre-scaled by log2e, duplicated
    u64 w2a[HID], w2b[HID], w2c[HID], w2d[HID];           // W2^T cols, pre-scaled by ln2, duplicated
    float b2[4];
    float t1;
};

// ---- f32x2 helpers ----
__device__ __forceinline__ u64 pk2(float a, float b) {
    u64 r; asm("mov.b64 %0, {%1, %2};" : "=l"(r) : "f"(a), "f"(b)); return r;
}
__device__ __forceinline__ void up2(u64 v, float& a, float& b) {
    asm("mov.b64 {%0, %1}, %2;" : "=f"(a), "=f"(b) : "l"(v));
}
__device__ __forceinline__ u64 fma2(u64 a, u64 b, u64 c) {
    u64 d; asm("fma.rn.f32x2 %0, %1, %2, %3;" : "=l"(d) : "l"(a), "l"(b), "l"(c)); return d;
}
__device__ __forceinline__ u64 add2(u64 a, u64 b) {
    u64 d; asm("add.rn.f32x2 %0, %1, %2;" : "=l"(d) : "l"(a), "l"(b)); return d;
}
__device__ __forceinline__ u64 neg2(u64 a) { return a ^ 0x8000000080000000ULL; }

struct P4 { u64 x, y, z, w; };

// ---- scalar MUFU helpers ----
__device__ __forceinline__ float ex2f(float x) {
    float y; asm("ex2.approx.f32 %0, %1;" : "=f"(y) : "f"(x)); return y;
}
__device__ __forceinline__ float lg2f(float x) {
    float y; asm("lg2.approx.f32 %0, %1;" : "=f"(y) : "f"(x)); return y;
}
__device__ __forceinline__ float rcpf(float x) {
    float y; asm("rcp.approx.f32 %0, %1;" : "=f"(y) : "f"(x)); return y;
}
__device__ __forceinline__ float tanh_f(float x) {
    const float c = -2.8853900817779268f;  // -2*log2(e)
    float t = ex2f(c * fabsf(x));
    float r = (1.0f - t) * rcpf(1.0f + t);
    return copysignf(r, x);
}
__device__ __forceinline__ float sp_f(float x) {     // softplus(x)/ln2, x pre-scaled by log2e
    return lg2f(1.0f + ex2f(x));
}

// Packed vector field: 2 elements at once, layer-2 fused.
__device__ __forceinline__ P4 vf(const WP& s, P4 Y) {
    u64 A0 = pk2(s.b2[0], s.b2[0]);
    u64 A1 = pk2(s.b2[1], s.b2[1]);
    u64 A2 = pk2(s.b2[2], s.b2[2]);
    u64 A3 = pk2(s.b2[3], s.b2[3]);
#pragma unroll
    for (int j = 0; j < HID; j++) {
        u64 x2 = s.b1[j];
        x2 = fma2(s.w1x[j], Y.x, x2);
        x2 = fma2(s.w1y[j], Y.y, x2);
        x2 = fma2(s.w1z[j], Y.z, x2);
        x2 = fma2(s.w1w[j], Y.w, x2);
        float xa, xb; up2(x2, xa, xb);
        u64 h2 = pk2(sp_f(xa), sp_f(xb));
        A0 = fma2(s.w2a[j], h2, A0);
        A1 = fma2(s.w2b[j], h2, A1);
        A2 = fma2(s.w2c[j], h2, A2);
        A3 = fma2(s.w2d[j], h2, A3);
    }
    float a, b;
    P4 F;
    up2(A0, a, b); F.x = pk2(tanh_f(a), tanh_f(b));
    up2(A1, a, b); F.y = pk2(tanh_f(a), tanh_f(b));
    up2(A2, a, b); F.z = pk2(tanh_f(a), tanh_f(b));
    up2(A3, a, b); F.w = pk2(tanh_f(a), tanh_f(b));
    return F;
}

__device__ __forceinline__ u64 sum4(P4 v) {
    return add2(add2(v.x, v.y), add2(v.z, v.w));
}

__global__ void __launch_bounds__(TPB, 8) ode_kernel(
    const float4* __restrict__ y0,
    const float*  __restrict__ W1,
    const float*  __restrict__ b1,
    const float*  __restrict__ W2,
    const float*  __restrict__ b2,
    const float*  __restrict__ t1p,
    float* __restrict__ out,
    int B)
{
    __shared__ WP s;
    __shared__ float warp_sums[TPB / 32];

    const float LOG2E = 1.4426950408889634f;
    const float LN2   = 0.6931471805599453f;

    int tid = threadIdx.x;
    if (tid < HID) {
        float4 w = reinterpret_cast<const float4*>(W1)[tid];
        s.w1x[tid] = pk2(w.x * LOG2E, w.x * LOG2E);
        s.w1y[tid] = pk2(w.y * LOG2E, w.y * LOG2E);
        s.w1z[tid] = pk2(w.z * LOG2E, w.z * LOG2E);
        s.w1w[tid] = pk2(w.w * LOG2E, w.w * LOG2E);
        float bb = b1[tid] * LOG2E;
        s.b1[tid] = pk2(bb, bb);
        float c0 = W2[0 * HID + tid] * LN2;
        float c1 = W2[1 * HID + tid] * LN2;
        float c2 = W2[2 * HID + tid] * LN2;
        float c3 = W2[3 * HID + tid] * LN2;
        s.w2a[tid] = pk2(c0, c0);
        s.w2b[tid] = pk2(c1, c1);
        s.w2c[tid] = pk2(c2, c2);
        s.w2d[tid] = pk2(c3, c3);
    }
    if (tid < 4) s.b2[tid] = b2[tid];
    if (tid == 0) s.t1 = t1p[0];
    __syncthreads();

    int pidx = blockIdx.x * TPB + tid;   // pair index
    int i0 = 2 * pidx;
    float ssum = 0.0f;

    if (i0 < B) {
        int i1 = (i0 + 1 < B) ? (i0 + 1) : i0;   // clamp; lane b masked below
        bool b_valid = (i0 + 1 < B);

        float4 ya = y0[i0];
        float4 yb = y0[i1];
        P4 Y;
        Y.x = pk2(ya.x, yb.x);
        Y.y = pk2(ya.y, yb.y);
        Y.z = pk2(ya.z, yb.z);
        Y.w = pk2(ya.w, yb.w);

        const float dt  = s.t1 * (1.0f / 3.0f);
        const float hdt = 0.5f * dt;
        const float c6  = dt * (1.0f / 6.0f);
        const float ch  = dt * (272.0f / 99.0f);
        const u64 HDT = pk2(hdt, hdt);
        const u64 DT  = pk2(dt, dt);
        const u64 C6  = pk2(c6, c6);
        const u64 CH  = pk2(ch, ch);
        const u64 C2  = pk2(2.0f, 2.0f);
        const u64 C16 = pk2(16.0f, 16.0f);
        const u64 C17 = pk2(17.0f, 17.0f);

        u64 S = sum4(Y);                 // save at t=0 (both lanes)
        P4 f = vf(s, Y);                 // k1 of first step

#pragma unroll 1
        for (int st = 0; st < NSTEP; st++) {
            // f == k1. Keep only its component-sum for the Hermite term; fold
            // k1 into the RK4 accumulator immediately (accumulate form keeps
            // at most {Y, kacc, yt} of state live across any vf call).
            u64 sf = sum4(f);

            P4 kacc = f;                           // kacc = k1
            P4 yt;
            yt.x = fma2(HDT, f.x, Y.x);
            yt.y = fma2(HDT, f.y, Y.y);
            yt.z = fma2(HDT, f.z, Y.z);
            yt.w = fma2(HDT, f.w, Y.w);

            P4 k = vf(s, yt);                      // k2
            kacc.x = fma2(C2, k.x, kacc.x);
            kacc.y = fma2(C2, k.y, kacc.y);
            kacc.z = fma2(C2, k.z, kacc.z);
            kacc.w = fma2(C2, k.w, kacc.w);
            yt.x = fma2(HDT, k.x, Y.x);
            yt.y = fma2(HDT, k.y, Y.y);
            yt.z = fma2(HDT, k.z, Y.z);
            yt.w = fma2(HDT, k.w, Y.w);

            k = vf(s, yt);                         // k3
            kacc.x = fma2(C2, k.x, kacc.x);
            kacc.y = fma2(C2, k.y, kacc.y);
            kacc.z = fma2(C2, k.z, kacc.z);
            kacc.w = fma2(C2, k.w, kacc.w);
            yt.x = fma2(DT, k.x, Y.x);
            yt.y = fma2(DT, k.y, Y.y);
            yt.z = fma2(DT, k.z, Y.z);
            yt.w = fma2(DT, k.w, Y.w);

            k = vf(s, yt);                         // k4
            kacc.x = add2(kacc.x, k.x);
            kacc.y = add2(kacc.y, k.y);
            kacc.z = add2(kacc.z, k.z);
            kacc.w = add2(kacc.w, k.w);

            P4 yn;
            yn.x = fma2(C6, kacc.x, Y.x);
            yn.y = fma2(C6, kacc.y, Y.y);
            yn.z = fma2(C6, kacc.z, Y.z);
            yn.w = fma2(C6, kacc.w, Y.w);

            P4 fn = vf(s, yn);                     // next step's k1 + right Hermite slope

            // 32 interior Hermite samples + endpoint save:
            //   16*(y+yn) + yn + (272/99)*h*(f-fn)
            u64 sy  = sum4(Y);
            u64 syn = sum4(yn);
            u64 sd  = add2(sf, neg2(sum4(fn)));
            S = fma2(C16, sy, S);
            S = fma2(C17, syn, S);
            S = fma2(CH, sd, S);

            Y = yn;
            f = fn;
        }

        float sa, sb; up2(S, sa, sb);
        ssum = sa + (b_valid ? sb : 0.0f);
    }

    // Block reduction -> per-block partial
#pragma unroll
    for (int o = 16; o > 0; o >>= 1)
        ssum += __shfl_xor_sync(0xFFFFFFFFu, ssum, o);
    int lane = tid & 31;
    int wid  = tid >> 5;
    if (lane == 0) warp_sums[wid] = ssum;
    __syncthreads();

    __shared__ bool is_last;
    if (tid == 0) {
        float bs = 0.0f;
#pragma unroll
        for (int w = 0; w < TPB / 32; w++) bs += warp_sums[w];
        g_partials[blockIdx.x] = bs;
        __threadfence();
        int prev = atomicAdd(&g_count, 1);
        is_last = (prev == gridDim.x - 1);
    }
    __syncthreads();

    // Last block: reduce all partials in double, write scalar, reset counter.
    if (is_last) {
        double acc = 0.0;
        for (int i = tid; i < gridDim.x; i += TPB)
            acc += (double)g_partials[i];
#pragma unroll
        for (int o = 16; o > 0; o >>= 1)
            acc += __shfl_xor_sync(0xFFFFFFFFu, acc, o);
        __shared__ double wsd[TPB / 32];
        if (lane == 0) wsd[wid] = acc;
        __syncthreads();
        if (tid == 0) {
            double tot = 0.0;
#pragma unroll
            for (int w = 0; w < TPB / 32; w++) tot += wsd[w];
            out[0] = (float)tot;
            g_count = 0;   // self-reset for next graph replay
        }
    }
}

extern "C" void kernel_launch(void* const* d_in, const int* in_sizes, int n_in,
                              void* d_out, int out_size) {
    const float* y0 = (const float*)d_in[0];
    const float* W1 = (const float*)d_in[1];
    const float* b1 = (const float*)d_in[2];
    const float* W2 = (const float*)d_in[3];
    const float* b2 = (const float*)d_in[4];
    const float* t1 = (const float*)d_in[5];
    float* out = (float*)d_out;

    int B = in_sizes[0] / 4;
    int pairs = (B + 1) / 2;                   // 65536
    int blocks = (pairs + TPB - 1) / TPB;      // 1024

    ode_kernel<<<blocks, TPB>>>(reinterpret_cast<const float4*>(y0),
                                W1, b1, W2, b2, t1, out, B);
}

// round 10
// speedup vs baseline: 1.1755x; 1.0008x over previous
#include <cuda_runtime.h>

// NeuralODETorch: 131072 independent 4-dim states, MLP field 4->32(softplus)->4(tanh).
// RK4 fixed step: 3 steps of h = t1/3, each covering 33 save-intervals.
// Cubic-Hermite dense output, 32 interior points per step collapsed:
//   sum_{k=1..32} H(k/33) = 16*(y+yn) + (272/99)*h*(f - fn).
// 2 batch elements per thread with packed f32x2 math (FFMA2); weights in shared
// pre-duplicated {w,w}. RK4 in accumulate form (k2/k3 never co-live) and f kept
// only as its component-sum, so the live set fits a 128-register cap (16 warps/SM).

#define HID 32
#define NSTEP 3
#define TPB 64
#define MAXBLOCKS 1024

typedef unsigned long long u64;

static __device__ float g_partials[MAXBLOCKS];
static __device__ int   g_count = 0;

struct WP {
    u64 w1x[HID], w1y[HID], w1z[HID], w1w[HID], b1[HID];  // pre-scaled by log2e, duplicated
    u64 w2a[HID], w2b[HID], w2c[HID], w2d[HID];           // W2^T cols, pre-scaled by ln2, duplicated
    float b2[4];
    float t1;
};

// ---- f32x2 helpers ----
__device__ __forceinline__ u64 pk2(float a, float b) {
    u64 r; asm("mov.b64 %0, {%1, %2};" : "=l"(r) : "f"(a), "f"(b)); return r;
}
__device__ __forceinline__ void up2(u64 v, float& a, float& b) {
    asm("mov.b64 {%0, %1}, %2;" : "=f"(a), "=f"(b) : "l"(v));
}
__device__ __forceinline__ u64 fma2(u64 a, u64 b, u64 c) {
    u64 d; asm("fma.rn.f32x2 %0, %1, %2, %3;" : "=l"(d) : "l"(a), "l"(b), "l"(c)); return d;
}
__device__ __forceinline__ u64 add2(u64 a, u64 b) {
    u64 d; asm("add.rn.f32x2 %0, %1, %2;" : "=l"(d) : "l"(a), "l"(b)); return d;
}
__device__ __forceinline__ u64 neg2(u64 a) { return a ^ 0x8000000080000000ULL; }

struct P4 { u64 x, y, z, w; };

// ---- scalar MUFU helpers ----
__device__ __forceinline__ float ex2f(float x) {
    float y; asm("ex2.approx.f32 %0, %1;" : "=f"(y) : "f"(x)); return y;
}
__device__ __forceinline__ float lg2f(float x) {
    float y; asm("lg2.approx.f32 %0, %1;" : "=f"(y) : "f"(x)); return y;
}
__device__ __forceinline__ float rcpf(float x) {
    float y; asm("rcp.approx.f32 %0, %1;" : "=f"(y) : "f"(x)); return y;
}
__device__ __forceinline__ float tanh_f(float x) {
    const float c = -2.8853900817779268f;  // -2*log2(e)
    float t = ex2f(c * fabsf(x));
    float r = (1.0f - t) * rcpf(1.0f + t);
    return copysignf(r, x);
}
__device__ __forceinline__ float sp_f(float x) {     // softplus(x)/ln2, x pre-scaled by log2e
    return lg2f(1.0f + ex2f(x));
}

// Packed vector field: 2 elements at once, layer-2 fused.
__device__ __forceinline__ P4 vf(const WP& s, P4 Y) {
    u64 A0 = pk2(s.b2[0], s.b2[0]);
    u64 A1 = pk2(s.b2[1], s.b2[1]);
    u64 A2 = pk2(s.b2[2], s.b2[2]);
    u64 A3 = pk2(s.b2[3], s.b2[3]);
#pragma unroll
    for (int j = 0; j < HID; j++) {
        u64 x2 = s.b1[j];
        x2 = fma2(s.w1x[j], Y.x, x2);
        x2 = fma2(s.w1y[j], Y.y, x2);
        x2 = fma2(s.w1z[j], Y.z, x2);
        x2 = fma2(s.w1w[j], Y.w, x2);
        float xa, xb; up2(x2, xa, xb);
        u64 h2 = pk2(sp_f(xa), sp_f(xb));
        A0 = fma2(s.w2a[j], h2, A0);
        A1 = fma2(s.w2b[j], h2, A1);
        A2 = fma2(s.w2c[j], h2, A2);
        A3 = fma2(s.w2d[j], h2, A3);
    }
    float a, b;
    P4 F;
    up2(A0, a, b); F.x = pk2(tanh_f(a), tanh_f(b));
    up2(A1, a, b); F.y = pk2(tanh_f(a), tanh_f(b));
    up2(A2, a, b); F.z = pk2(tanh_f(a), tanh_f(b));
    up2(A3, a, b); F.w = pk2(tanh_f(a), tanh_f(b));
    return F;
}

__device__ __forceinline__ u64 sum4(P4 v) {
    return add2(add2(v.x, v.y), add2(v.z, v.w));
}

__global__ void __launch_bounds__(TPB, 8) ode_kernel(
    const float4* __restrict__ y0,
    const float*  __restrict__ W1,
    const float*  __restrict__ b1,
    const float*  __restrict__ W2,
    const float*  __restrict__ b2,
    const float*  __restrict__ t1p,
    float* __restrict__ out,
    int B)
{
    __shared__ WP s;
    __shared__ float warp_sums[TPB / 32];

    const float LOG2E = 1.4426950408889634f;
    const float LN2   = 0.6931471805599453f;

    int tid = threadIdx.x;
    if (tid < HID) {
        float4 w = reinterpret_cast<const float4*>(W1)[tid];
        s.w1x[tid] = pk2(w.x * LOG2E, w.x * LOG2E);
        s.w1y[tid] = pk2(w.y * LOG2E, w.y * LOG2E);
        s.w1z[tid] = pk2(w.z * LOG2E, w.z * LOG2E);
        s.w1w[tid] = pk2(w.w * LOG2E, w.w * LOG2E);
        float bb = b1[tid] * LOG2E;
        s.b1[tid] = pk2(bb, bb);
        float c0 = W2[0 * HID + tid] * LN2;
        float c1 = W2[1 * HID + tid] * LN2;
        float c2 = W2[2 * HID + tid] * LN2;
        float c3 = W2[3 * HID + tid] * LN2;
        s.w2a[tid] = pk2(c0, c0);
        s.w2b[tid] = pk2(c1, c1);
        s.w2c[tid] = pk2(c2, c2);
        s.w2d[tid] = pk2(c3, c3);
    }
    if (tid < 4) s.b2[tid] = b2[tid];
    if (tid == 0) s.t1 = t1p[0];
    __syncthreads();

    int pidx = blockIdx.x * TPB + tid;   // pair index
    int i0 = 2 * pidx;
    float ssum = 0.0f;

    if (i0 < B) {
        int i1 = (i0 + 1 < B) ? (i0 + 1) : i0;   // clamp; lane b masked below
        bool b_valid = (i0 + 1 < B);

        float4 ya = y0[i0];
        float4 yb = y0[i1];
        P4 Y;
        Y.x = pk2(ya.x, yb.x);
        Y.y = pk2(ya.y, yb.y);
        Y.z = pk2(ya.z, yb.z);
        Y.w = pk2(ya.w, yb.w);

        const float dt  = s.t1 * (1.0f / 3.0f);
        const float hdt = 0.5f * dt;
        const float c6  = dt * (1.0f / 6.0f);
        const float ch  = dt * (272.0f / 99.0f);
        const u64 HDT = pk2(hdt, hdt);
        const u64 DT  = pk2(dt, dt);
        const u64 C6  = pk2(c6, c6);
        const u64 CH  = pk2(ch, ch);
        const u64 C2  = pk2(2.0f, 2.0f);
        const u64 C16 = pk2(16.0f, 16.0f);
        const u64 C17 = pk2(17.0f, 17.0f);

        u64 S = sum4(Y);                 // save at t=0 (both lanes)
        P4 f = vf(s, Y);                 // k1 of first step

#pragma unroll 1
        for (int st = 0; st < NSTEP; st++) {
            // f == k1. Keep only its component-sum for the Hermite term; fold
            // k1 into the RK4 accumulator immediately (accumulate form keeps
            // at most {Y, kacc, yt} of state live across any vf call).
            u64 sf = sum4(f);

            P4 kacc = f;                           // kacc = k1
            P4 yt;
            yt.x = fma2(HDT, f.x, Y.x);
            yt.y = fma2(HDT, f.y, Y.y);
            yt.z = fma2(HDT, f.z, Y.z);
            yt.w = fma2(HDT, f.w, Y.w);

            P4 k = vf(s, yt);                      // k2
            kacc.x = fma2(C2, k.x, kacc.x);
            kacc.y = fma2(C2, k.y, kacc.y);
            kacc.z = fma2(C2, k.z, kacc.z);
            kacc.w = fma2(C2, k.w, kacc.w);
            yt.x = fma2(HDT, k.x, Y.x);
            yt.y = fma2(HDT, k.y, Y.y);
            yt.z = fma2(HDT, k.z, Y.z);
            yt.w = fma2(HDT, k.w, Y.w);

            k = vf(s, yt);                         // k3
            kacc.x = fma2(C2, k.x, kacc.x);
            kacc.y = fma2(C2, k.y, kacc.y);
            kacc.z = fma2(C2, k.z, kacc.z);
            kacc.w = fma2(C2, k.w, kacc.w);
            yt.x = fma2(DT, k.x, Y.x);
            yt.y = fma2(DT, k.y, Y.y);
            yt.z = fma2(DT, k.z, Y.z);
            yt.w = fma2(DT, k.w, Y.w);

            k = vf(s, yt);                         // k4
            kacc.x = add2(kacc.x, k.x);
            kacc.y = add2(kacc.y, k.y);
            kacc.z = add2(kacc.z, k.z);
            kacc.w = add2(kacc.w, k.w);

            P4 yn;
            yn.x = fma2(C6, kacc.x, Y.x);
            yn.y = fma2(C6, kacc.y, Y.y);
            yn.z = fma2(C6, kacc.z, Y.z);
            yn.w = fma2(C6, kacc.w, Y.w);

            P4 fn = vf(s, yn);                     // next step's k1 + right Hermite slope

            // 32 interior Hermite samples + endpoint save:
            //   16*(y+yn) + yn + (272/99)*h*(f-fn)
            u64 sy  = sum4(Y);
            u64 syn = sum4(yn);
            u64 sd  = add2(sf, neg2(sum4(fn)));
            S = fma2(C16, sy, S);
            S = fma2(C17, syn, S);
            S = fma2(CH, sd, S);

            Y = yn;
            f = fn;
        }

        float sa, sb; up2(S, sa, sb);
        ssum = sa + (b_valid ? sb : 0.0f);
    }

    // Block reduction -> per-block partial
#pragma unroll
    for (int o = 16; o > 0; o >>= 1)
        ssum += __shfl_xor_sync(0xFFFFFFFFu, ssum, o);
    int lane = tid & 31;
    int wid  = tid >> 5;
    if (lane == 0) warp_sums[wid] = ssum;
    __syncthreads();

    __shared__ bool is_last;
    if (tid == 0) {
        float bs = 0.0f;
#pragma unroll
        for (int w = 0; w < TPB / 32; w++) bs += warp_sums[w];
        g_partials[blockIdx.x] = bs;
        __threadfence();
        int prev = atomicAdd(&g_count, 1);
        is_last = (prev == gridDim.x - 1);
    }
    __syncthreads();

    // Last block: reduce all partials in double, write scalar, reset counter.
    if (is_last) {
        double acc = 0.0;
        for (int i = tid; i < gridDim.x; i += TPB)
            acc += (double)g_partials[i];
#pragma unroll
        for (int o = 16; o > 0; o >>= 1)
            acc += __shfl_xor_sync(0xFFFFFFFFu, acc, o);
        __shared__ double wsd[TPB / 32];
        if (lane == 0) wsd[wid] = acc;
        __syncthreads();
        if (tid == 0) {
            double tot = 0.0;
#pragma unroll
            for (int w = 0; w < TPB / 32; w++) tot += wsd[w];
            out[0] = (float)tot;
            g_count = 0;   // self-reset for next graph replay
        }
    }
}

extern "C" void kernel_launch(void* const* d_in, const int* in_sizes, int n_in,
                              void* d_out, int out_size) {
    const float* y0 = (const float*)d_in[0];
    const float* W1 = (const float*)d_in[1];
    const float* b1 = (const float*)d_in[2];
    const float* W2 = (const float*)d_in[3];
    const float* b2 = (const float*)d_in[4];
    const float* t1 = (const float*)d_in[5];
    float* out = (float*)d_out;

    int B = in_sizes[0] / 4;
    int pairs = (B + 1) / 2;                   // 65536
    int blocks = (pairs + TPB - 1) / TPB;      // 1024

    ode_kernel<<<blocks, TPB>>>(reinterpret_cast<const float4*>(y0),
                                W1, b1, W2, b2, t1, out, B);
}

// round 11
// speedup vs baseline: 2.8100x; 2.3905x over previous
#include <cuda_runtime.h>

// NeuralODETorch: 131072 independent 4-dim states, MLP field 4->32(softplus)->4(tanh).
// RK4 fixed step: 3 steps of h = t1/3, each covering 33 save-intervals.
// Cubic-Hermite dense output, 32 interior points per step collapsed:
//   sum_{k=1..32} H(k/33) = 16*(y+yn) + (272/99)*h*(f - fn).
// Scalar math (round-5 lineage; f32x2 abandoned — reg-pair fragmentation spills).
// Accumulate-form RK4 shrinks the live set; __launch_bounds__(128,4) caps regs
// at 128 -> 16 warps/SM without spills.

#define HID 32
#define NSTEP 3
#define TPB 128
#define MAXBLOCKS 1024

static __device__ float g_partials[MAXBLOCKS];
static __device__ int   g_count = 0;

struct Weights {
    float4 W1[HID];    // row j, pre-scaled by log2e
    float  b1[HID];    // pre-scaled by log2e
    float4 W2t[HID];   // column j of W2 (4 outputs), pre-scaled by ln2
    float  b2[4];
    float  t1;
};

__device__ __forceinline__ float ex2f(float x) {
    float y; asm("ex2.approx.f32 %0, %1;" : "=f"(y) : "f"(x)); return y;
}
__device__ __forceinline__ float lg2f(float x) {
    float y; asm("lg2.approx.f32 %0, %1;" : "=f"(y) : "f"(x)); return y;
}
__device__ __forceinline__ float rcpf(float x) {
    float y; asm("rcp.approx.f32 %0, %1;" : "=f"(y) : "f"(x)); return y;
}

__device__ __forceinline__ float tanh_f(float x) {
    // tanh(x) = sign(x)*(1-t)/(1+t), t = exp(-2|x|) = ex2(-2*log2e*|x|)
    const float c = -2.8853900817779268f;  // -2*log2(e)
    float t = ex2f(c * fabsf(x));
    float r = (1.0f - t) * rcpf(1.0f + t);
    return copysignf(r, x);
}

// Vector field with layer-2 fused into the hidden loop (no hb array).
__device__ __forceinline__ float4 vf(const Weights& s, float4 y) {
    float a0 = s.b2[0], a1 = s.b2[1], a2 = s.b2[2], a3 = s.b2[3];
#pragma unroll
    for (int j = 0; j < HID; j++) {
        float4 w = s.W1[j];
        float x = s.b1[j];
        x = fmaf(w.x, y.x, x);
        x = fmaf(w.y, y.y, x);
        x = fmaf(w.z, y.z, x);
        x = fmaf(w.w, y.w, x);
        float hv = lg2f(1.0f + ex2f(x));   // softplus / ln2 (ln2 folded into W2t)
        float4 w2 = s.W2t[j];
        a0 = fmaf(w2.x, hv, a0);
        a1 = fmaf(w2.y, hv, a1);
        a2 = fmaf(w2.z, hv, a2);
        a3 = fmaf(w2.w, hv, a3);
    }
    float4 o;
    o.x = tanh_f(a0);
    o.y = tanh_f(a1);
    o.z = tanh_f(a2);
    o.w = tanh_f(a3);
    return o;
}

__global__ void __launch_bounds__(TPB, 4) ode_kernel(
    const float4* __restrict__ y0,
    const float*  __restrict__ W1,
    const float*  __restrict__ b1,
    const float*  __restrict__ W2,
    const float*  __restrict__ b2,
    const float*  __restrict__ t1p,
    float* __restrict__ out,
    int B)
{
    __shared__ Weights s;
    __shared__ float warp_sums[TPB / 32];

    const float LOG2E = 1.4426950408889634f;
    const float LN2   = 0.6931471805599453f;

    int tid = threadIdx.x;
    if (tid < HID) {
        float4 w = reinterpret_cast<const float4*>(W1)[tid];
        w.x *= LOG2E; w.y *= LOG2E; w.z *= LOG2E; w.w *= LOG2E;
        s.W1[tid] = w;
        s.b1[tid] = b1[tid] * LOG2E;
        float4 c;
        c.x = W2[0 * HID + tid] * LN2;
        c.y = W2[1 * HID + tid] * LN2;
        c.z = W2[2 * HID + tid] * LN2;
        c.w = W2[3 * HID + tid] * LN2;
        s.W2t[tid] = c;
    }
    if (tid < 4) s.b2[tid] = b2[tid];
    if (tid == 0) s.t1 = t1p[0];
    __syncthreads();

    int idx = blockIdx.x * TPB + tid;
    float ssum = 0.0f;

    if (idx < B) {
        float4 y = y0[idx];
        const float dt  = s.t1 * (1.0f / 3.0f);   // h = t1/3
        const float hdt = 0.5f * dt;
        const float c6  = dt * (1.0f / 6.0f);
        const float ch  = dt * (272.0f / 99.0f);  // Hermite interior-sum slope coeff

        ssum = y.x + y.y + y.z + y.w;             // save at t=0
        float4 f = vf(s, y);                      // k1 of first step

#pragma unroll 1
        for (int st = 0; st < NSTEP; st++) {
            // f == k1; keep only its component-sum for the Hermite term and
            // fold k1 into the accumulator immediately. Live across any vf
            // call: {y, kacc, sf, ssum, consts} only.
            float sf = f.x + f.y + f.z + f.w;

            float4 kacc = f;
            float4 yt;
            yt.x = fmaf(hdt, f.x, y.x);
            yt.y = fmaf(hdt, f.y, y.y);
            yt.z = fmaf(hdt, f.z, y.z);
            yt.w = fmaf(hdt, f.w, y.w);

            float4 k = vf(s, yt);                 // k2
            kacc.x = fmaf(2.0f, k.x, kacc.x);
            kacc.y = fmaf(2.0f, k.y, kacc.y);
            kacc.z = fmaf(2.0f, k.z, kacc.z);
            kacc.w = fmaf(2.0f, k.w, kacc.w);
            yt.x = fmaf(hdt, k.x, y.x);
            yt.y = fmaf(hdt, k.y, y.y);
            yt.z = fmaf(hdt, k.z, y.z);
            yt.w = fmaf(hdt, k.w, y.w);

            k = vf(s, yt);                        // k3
            kacc.x = fmaf(2.0f, k.x, kacc.x);
            kacc.y = fmaf(2.0f, k.y, kacc.y);
            kacc.z = fmaf(2.0f, k.z, kacc.z);
            kacc.w = fmaf(2.0f, k.w, kacc.w);
            yt.x = fmaf(dt, k.x, y.x);
            yt.y = fmaf(dt, k.y, y.y);
            yt.z = fmaf(dt, k.z, y.z);
            yt.w = fmaf(dt, k.w, y.w);

            k = vf(s, yt);                        // k4
            kacc.x += k.x;
            kacc.y += k.y;
            kacc.z += k.z;
            kacc.w += k.w;

            float4 yn;
            yn.x = fmaf(c6, kacc.x, y.x);
            yn.y = fmaf(c6, kacc.y, y.y);
            yn.z = fmaf(c6, kacc.z, y.z);
            yn.w = fmaf(c6, kacc.w, y.w);

            float4 fn = vf(s, yn);                // next step's k1 + right Hermite slope

            // 32 interior Hermite samples + endpoint save:
            //   16*(y + yn) + yn + (272/99)*h*(f - fn)
            float sy  = y.x + y.y + y.z + y.w;
            float syn = yn.x + yn.y + yn.z + yn.w;
            float sfn = fn.x + fn.y + fn.z + fn.w;
            ssum += 16.0f * sy + 17.0f * syn + ch * (sf - sfn);

            y = yn;
            f = fn;
        }
    }

    // Block reduction -> per-block partial
#pragma unroll
    for (int o = 16; o > 0; o >>= 1)
        ssum += __shfl_xor_sync(0xFFFFFFFFu, ssum, o);
    int lane = tid & 31;
    int wid  = tid >> 5;
    if (lane == 0) warp_sums[wid] = ssum;
    __syncthreads();

    __shared__ bool is_last;
    if (tid == 0) {
        float bs = 0.0f;
#pragma unroll
        for (int w = 0; w < TPB / 32; w++) bs += warp_sums[w];
        g_partials[blockIdx.x] = bs;
        __threadfence();
        int prev = atomicAdd(&g_count, 1);
        is_last = (prev == gridDim.x - 1);
    }
    __syncthreads();

    // Last block: reduce all partials in double, write scalar, reset counter.
    if (is_last) {
        double acc = 0.0;
        for (int i = tid; i < gridDim.x; i += TPB)
            acc += (double)g_partials[i];
#pragma unroll
        for (int o = 16; o > 0; o >>= 1)
            acc += __shfl_xor_sync(0xFFFFFFFFu, acc, o);
        __shared__ double wsd[TPB / 32];
        if (lane == 0) wsd[wid] = acc;
        __syncthreads();
        if (tid == 0) {
            double tot = 0.0;
#pragma unroll
            for (int w = 0; w < TPB / 32; w++) tot += wsd[w];
            out[0] = (float)tot;
            g_count = 0;   // self-reset for next graph replay
        }
    }
}

extern "C" void kernel_launch(void* const* d_in, const int* in_sizes, int n_in,
                              void* d_out, int out_size) {
    const float* y0 = (const float*)d_in[0];
    const float* W1 = (const float*)d_in[1];
    const float* b1 = (const float*)d_in[2];
    const float* W2 = (const float*)d_in[3];
    const float* b2 = (const float*)d_in[4];
    const float* t1 = (const float*)d_in[5];
    float* out = (float*)d_out;

    int B = in_sizes[0] / 4;
    int blocks = (B + TPB - 1) / TPB;   // 1024 for B=131072

    ode_kernel<<<blocks, TPB>>>(reinterpret_cast<const float4*>(y0),
                                W1, b1, W2, b2, t1, out, B);
}

// round 16
// speedup vs baseline: 3.0213x; 1.0752x over previous
#include <cuda_runtime.h>

// NeuralODETorch: 131072 independent 4-dim states, MLP field 4->32(softplus)->4(tanh).
// RK4 fixed step: 3 steps of h = t1/3, each covering 33 save-intervals.
// Cubic-Hermite dense output, 32 interior points per step collapsed:
//   sum_{k=1..32} H(k/33) = 16*(y+yn) + (272/99)*h*(f - fn).
// Scalar math, accumulate-form RK4. Register-cap probe: (128,4)=128 spilled
// (97us), uncapped=255 ran 51.7us at 8 warps/SM. This round: (128,3)=170 regs
// -> 12 warps/SM, expected spill-free.

#define HID 32
#define NSTEP 3
#define TPB 128
#define MAXBLOCKS 1024

static __device__ float g_partials[MAXBLOCKS];
static __device__ int   g_count = 0;

struct Weights {
    float4 W1[HID];    // row j, pre-scaled by log2e
    float  b1[HID];    // pre-scaled by log2e
    float4 W2t[HID];   // column j of W2 (4 outputs), pre-scaled by ln2
    float  b2[4];
    float  t1;
};

__device__ __forceinline__ float ex2f(float x) {
    float y; asm("ex2.approx.f32 %0, %1;" : "=f"(y) : "f"(x)); return y;
}
__device__ __forceinline__ float lg2f(float x) {
    float y; asm("lg2.approx.f32 %0, %1;" : "=f"(y) : "f"(x)); return y;
}
__device__ __forceinline__ float rcpf(float x) {
    float y; asm("rcp.approx.f32 %0, %1;" : "=f"(y) : "f"(x)); return y;
}

__device__ __forceinline__ float tanh_f(float x) {
    // tanh(x) = sign(x)*(1-t)/(1+t), t = exp(-2|x|) = ex2(-2*log2e*|x|)
    const float c = -2.8853900817779268f;  // -2*log2(e)
    float t = ex2f(c * fabsf(x));
    float r = (1.0f - t) * rcpf(1.0f + t);
    return copysignf(r, x);
}

// Vector field with layer-2 fused into the hidden loop (no hb array).
__device__ __forceinline__ float4 vf(const Weights& s, float4 y) {
    float a0 = s.b2[0], a1 = s.b2[1], a2 = s.b2[2], a3 = s.b2[3];
#pragma unroll
    for (int j = 0; j < HID; j++) {
        float4 w = s.W1[j];
        float x = s.b1[j];
        x = fmaf(w.x, y.x, x);
        x = fmaf(w.y, y.y, x);
        x = fmaf(w.z, y.z, x);
        x = fmaf(w.w, y.w, x);
        float hv = lg2f(1.0f + ex2f(x));   // softplus / ln2 (ln2 folded into W2t)
        float4 w2 = s.W2t[j];
        a0 = fmaf(w2.x, hv, a0);
        a1 = fmaf(w2.y, hv, a1);
        a2 = fmaf(w2.z, hv, a2);
        a3 = fmaf(w2.w, hv, a3);
    }
    float4 o;
    o.x = tanh_f(a0);
    o.y = tanh_f(a1);
    o.z = tanh_f(a2);
    o.w = tanh_f(a3);
    return o;
}

__global__ void __launch_bounds__(TPB, 3) ode_kernel(
    const float4* __restrict__ y0,
    const float*  __restrict__ W1,
    const float*  __restrict__ b1,
    const float*  __restrict__ W2,
    const float*  __restrict__ b2,
    const float*  __restrict__ t1p,
    float* __restrict__ out,
    int B)
{
    __shared__ Weights s;
    __shared__ float warp_sums[TPB / 32];

    const float LOG2E = 1.4426950408889634f;
    const float LN2   = 0.6931471805599453f;

    int tid = threadIdx.x;
    if (tid < HID) {
        float4 w = reinterpret_cast<const float4*>(W1)[tid];
        w.x *= LOG2E; w.y *= LOG2E; w.z *= LOG2E; w.w *= LOG2E;
        s.W1[tid] = w;
        s.b1[tid] = b1[tid] * LOG2E;
        float4 c;
        c.x = W2[0 * HID + tid] * LN2;
        c.y = W2[1 * HID + tid] * LN2;
        c.z = W2[2 * HID + tid] * LN2;
        c.w = W2[3 * HID + tid] * LN2;
        s.W2t[tid] = c;
    }
    if (tid < 4) s.b2[tid] = b2[tid];
    if (tid == 0) s.t1 = t1p[0];
    __syncthreads();

    int idx = blockIdx.x * TPB + tid;
    float ssum = 0.0f;

    if (idx < B) {
        float4 y = y0[idx];
        const float dt  = s.t1 * (1.0f / 3.0f);   // h = t1/3
        const float hdt = 0.5f * dt;
        const float c6  = dt * (1.0f / 6.0f);
        const float ch  = dt * (272.0f / 99.0f);  // Hermite interior-sum slope coeff

        ssum = y.x + y.y + y.z + y.w;             // save at t=0
        float4 f = vf(s, y);                      // k1 of first step

#pragma unroll 1
        for (int st = 0; st < NSTEP; st++) {
            // f == k1; keep only its component-sum for the Hermite term and
            // fold k1 into the accumulator immediately. Live across any vf
            // call: {y, kacc, sf, ssum, consts} only.
            float sf = f.x + f.y + f.z + f.w;

            float4 kacc = f;
            float4 yt;
            yt.x = fmaf(hdt, f.x, y.x);
            yt.y = fmaf(hdt, f.y, y.y);
            yt.z = fmaf(hdt, f.z, y.z);
            yt.w = fmaf(hdt, f.w, y.w);

            float4 k = vf(s, yt);                 // k2
            kacc.x = fmaf(2.0f, k.x, kacc.x);
            kacc.y = fmaf(2.0f, k.y, kacc.y);
            kacc.z = fmaf(2.0f, k.z, kacc.z);
            kacc.w = fmaf(2.0f, k.w, kacc.w);
            yt.x = fmaf(hdt, k.x, y.x);
            yt.y = fmaf(hdt, k.y, y.y);
            yt.z = fmaf(hdt, k.z, y.z);
            yt.w = fmaf(hdt, k.w, y.w);

            k = vf(s, yt);                        // k3
            kacc.x = fmaf(2.0f, k.x, kacc.x);
            kacc.y = fmaf(2.0f, k.y, kacc.y);
            kacc.z = fmaf(2.0f, k.z, kacc.z);
            kacc.w = fmaf(2.0f, k.w, kacc.w);
            yt.x = fmaf(dt, k.x, y.x);
            yt.y = fmaf(dt, k.y, y.y);
            yt.z = fmaf(dt, k.z, y.z);
            yt.w = fmaf(dt, k.w, y.w);

            k = vf(s, yt);                        // k4
            kacc.x += k.x;
            kacc.y += k.y;
            kacc.z += k.z;
            kacc.w += k.w;

            float4 yn;
            yn.x = fmaf(c6, kacc.x, y.x);
            yn.y = fmaf(c6, kacc.y, y.y);
            yn.z = fmaf(c6, kacc.z, y.z);
            yn.w = fmaf(c6, kacc.w, y.w);

            float4 fn = vf(s, yn);                // next step's k1 + right Hermite slope

            // 32 interior Hermite samples + endpoint save:
            //   16*(y + yn) + yn + (272/99)*h*(f - fn)
            float sy  = y.x + y.y + y.z + y.w;
            float syn = yn.x + yn.y + yn.z + yn.w;
            float sfn = fn.x + fn.y + fn.z + fn.w;
            ssum += 16.0f * sy + 17.0f * syn + ch * (sf - sfn);

            y = yn;
            f = fn;
        }
    }

    // Block reduction -> per-block partial
#pragma unroll
    for (int o = 16; o > 0; o >>= 1)
        ssum += __shfl_xor_sync(0xFFFFFFFFu, ssum, o);
    int lane = tid & 31;
    int wid  = tid >> 5;
    if (lane == 0) warp_sums[wid] = ssum;
    __syncthreads();

    __shared__ bool is_last;
    if (tid == 0) {
        float bs = 0.0f;
#pragma unroll
        for (int w = 0; w < TPB / 32; w++) bs += warp_sums[w];
        g_partials[blockIdx.x] = bs;
        __threadfence();
        int prev = atomicAdd(&g_count, 1);
        is_last = (prev == gridDim.x - 1);
    }
    __syncthreads();

    // Last block: reduce all partials in double, write scalar, reset counter.
    if (is_last) {
        double acc = 0.0;
        for (int i = tid; i < gridDim.x; i += TPB)
            acc += (double)g_partials[i];
#pragma unroll
        for (int o = 16; o > 0; o >>= 1)
            acc += __shfl_xor_sync(0xFFFFFFFFu, acc, o);
        __shared__ double wsd[TPB / 32];
        if (lane == 0) wsd[wid] = acc;
        __syncthreads();
        if (tid == 0) {
            double tot = 0.0;
#pragma unroll
            for (int w = 0; w < TPB / 32; w++) tot += wsd[w];
            out[0] = (float)tot;
            g_count = 0;   // self-reset for next graph replay
        }
    }
}

extern "C" void kernel_launch(void* const* d_in, const int* in_sizes, int n_in,
                              void* d_out, int out_size) {
    const float* y0 = (const float*)d_in[0];
    const float* W1 = (const float*)d_in[1];
    const float* b1 = (const float*)d_in[2];
    const float* W2 = (const float*)d_in[3];
    const float* b2 = (const float*)d_in[4];
    const float* t1 = (const float*)d_in[5];
    float* out = (float*)d_out;

    int B = in_sizes[0] / 4;
    int blocks = (B + TPB - 1) / TPB;   // 1024 for B=131072

    ode_kernel<<<blocks, TPB>>>(reinterpret_cast<const float4*>(y0),
                                W1, b1, W2, b2, t1, out, B);
}

// round 17
// speedup vs baseline: 6.5944x; 2.1827x over previous
#include <cuda_runtime.h>

// NeuralODETorch: 131072 independent 4-dim states, MLP field 4->32(softplus)->4(tanh).
// RK4 fixed step: 3 steps of h = t1/3, each covering 33 save-intervals.
// Cubic-Hermite dense output, 32 interior points per step collapsed:
//   sum_{k=1..32} H(k/33) = 16*(y+yn) + (272/99)*h*(f - fn).
// Scalar math, accumulate-form RK4. Register-pressure fix: the fully-unrolled
// hidden loop made ptxas hoist 32 iterations of LDS+chains (demand 171-255
// regs; caps of 128/170 both spilled). Partial unroll (8) shrinks the
// scheduling window so a 128-reg cap holds spill-free at 16 warps/SM.

#define HID 32
#define NSTEP 3
#define TPB 128
#define MAXBLOCKS 1024

static __device__ float g_partials[MAXBLOCKS];
static __device__ int   g_count = 0;

struct Weights {
    float4 W1[HID];    // row j, pre-scaled by log2e
    float  b1[HID];    // pre-scaled by log2e
    float4 W2t[HID];   // column j of W2 (4 outputs), pre-scaled by ln2
    float  b2[4];
    float  t1;
};

__device__ __forceinline__ float ex2f(float x) {
    float y; asm("ex2.approx.f32 %0, %1;" : "=f"(y) : "f"(x)); return y;
}
__device__ __forceinline__ float lg2f(float x) {
    float y; asm("lg2.approx.f32 %0, %1;" : "=f"(y) : "f"(x)); return y;
}
__device__ __forceinline__ float rcpf(float x) {
    float y; asm("rcp.approx.f32 %0, %1;" : "=f"(y) : "f"(x)); return y;
}

__device__ __forceinline__ float tanh_f(float x) {
    // tanh(x) = sign(x)*(1-t)/(1+t), t = exp(-2|x|) = ex2(-2*log2e*|x|)
    const float c = -2.8853900817779268f;  // -2*log2(e)
    float t = ex2f(c * fabsf(x));
    float r = (1.0f - t) * rcpf(1.0f + t);
    return copysignf(r, x);
}

// Vector field with layer-2 fused into the hidden loop (no hb array).
// Partial unroll: 8 independent activation chains in flight — enough ILP to
// cover the ~60-cycle chain latency, small enough to fit 128 registers.
__device__ __forceinline__ float4 vf(const Weights& s, float4 y) {
    float a0 = s.b2[0], a1 = s.b2[1], a2 = s.b2[2], a3 = s.b2[3];
#pragma unroll 8
    for (int j = 0; j < HID; j++) {
        float4 w = s.W1[j];
        float x = s.b1[j];
        x = fmaf(w.x, y.x, x);
        x = fmaf(w.y, y.y, x);
        x = fmaf(w.z, y.z, x);
        x = fmaf(w.w, y.w, x);
        float hv = lg2f(1.0f + ex2f(x));   // softplus / ln2 (ln2 folded into W2t)
        float4 w2 = s.W2t[j];
        a0 = fmaf(w2.x, hv, a0);
        a1 = fmaf(w2.y, hv, a1);
        a2 = fmaf(w2.z, hv, a2);
        a3 = fmaf(w2.w, hv, a3);
    }
    float4 o;
    o.x = tanh_f(a0);
    o.y = tanh_f(a1);
    o.z = tanh_f(a2);
    o.w = tanh_f(a3);
    return o;
}

__global__ void __launch_bounds__(TPB, 4) ode_kernel(
    const float4* __restrict__ y0,
    const float*  __restrict__ W1,
    const float*  __restrict__ b1,
    const float*  __restrict__ W2,
    const float*  __restrict__ b2,
    const float*  __restrict__ t1p,
    float* __restrict__ out,
    int B)
{
    __shared__ Weights s;
    __shared__ float warp_sums[TPB / 32];

    const float LOG2E = 1.4426950408889634f;
    const float LN2   = 0.6931471805599453f;

    int tid = threadIdx.x;
    if (tid < HID) {
        float4 w = reinterpret_cast<const float4*>(W1)[tid];
        w.x *= LOG2E; w.y *= LOG2E; w.z *= LOG2E; w.w *= LOG2E;
        s.W1[tid] = w;
        s.b1[tid] = b1[tid] * LOG2E;
        float4 c;
        c.x = W2[0 * HID + tid] * LN2;
        c.y = W2[1 * HID + tid] * LN2;
        c.z = W2[2 * HID + tid] * LN2;
        c.w = W2[3 * HID + tid] * LN2;
        s.W2t[tid] = c;
    }
    if (tid < 4) s.b2[tid] = b2[tid];
    if (tid == 0) s.t1 = t1p[0];
    __syncthreads();

    int idx = blockIdx.x * TPB + tid;
    float ssum = 0.0f;

    if (idx < B) {
        float4 y = y0[idx];
        const float dt  = s.t1 * (1.0f / 3.0f);   // h = t1/3
        const float hdt = 0.5f * dt;
        const float c6  = dt * (1.0f / 6.0f);
        const float ch  = dt * (272.0f / 99.0f);  // Hermite interior-sum slope coeff

        ssum = y.x + y.y + y.z + y.w;             // save at t=0
        float4 f = vf(s, y);                      // k1 of first step

#pragma unroll 1
        for (int st = 0; st < NSTEP; st++) {
            // f == k1; keep only its component-sum for the Hermite term and
            // fold k1 into the accumulator immediately. Live across any vf
            // call: {y, kacc, sf, ssum, consts} only.
            float sf = f.x + f.y + f.z + f.w;

            float4 kacc = f;
            float4 yt;
            yt.x = fmaf(hdt, f.x, y.x);
            yt.y = fmaf(hdt, f.y, y.y);
            yt.z = fmaf(hdt, f.z, y.z);
            yt.w = fmaf(hdt, f.w, y.w);

            float4 k = vf(s, yt);                 // k2
            kacc.x = fmaf(2.0f, k.x, kacc.x);
            kacc.y = fmaf(2.0f, k.y, kacc.y);
            kacc.z = fmaf(2.0f, k.z, kacc.z);
            kacc.w = fmaf(2.0f, k.w, kacc.w);
            yt.x = fmaf(hdt, k.x, y.x);
            yt.y = fmaf(hdt, k.y, y.y);
            yt.z = fmaf(hdt, k.z, y.z);
            yt.w = fmaf(hdt, k.w, y.w);

            k = vf(s, yt);                        // k3
            kacc.x = fmaf(2.0f, k.x, kacc.x);
            kacc.y = fmaf(2.0f, k.y, kacc.y);
            kacc.z = fmaf(2.0f, k.z, kacc.z);
            kacc.w = fmaf(2.0f, k.w, kacc.w);
            yt.x = fmaf(dt, k.x, y.x);
            yt.y = fmaf(dt, k.y, y.y);
            yt.z = fmaf(dt, k.z, y.z);
            yt.w = fmaf(dt, k.w, y.w);

            k = vf(s, yt);                        // k4
            kacc.x += k.x;
            kacc.y += k.y;
            kacc.z += k.z;
            kacc.w += k.w;

            float4 yn;
            yn.x = fmaf(c6, kacc.x, y.x);
            yn.y = fmaf(c6, kacc.y, y.y);
            yn.z = fmaf(c6, kacc.z, y.z);
            yn.w = fmaf(c6, kacc.w, y.w);

            float4 fn = vf(s, yn);                // next step's k1 + right Hermite slope

            // 32 interior Hermite samples + endpoint save:
            //   16*(y + yn) + yn + (272/99)*h*(f - fn)
            float sy  = y.x + y.y + y.z + y.w;
            float syn = yn.x + yn.y + yn.z + yn.w;
            float sfn = fn.x + fn.y + fn.z + fn.w;
            ssum += 16.0f * sy + 17.0f * syn + ch * (sf - sfn);

            y = yn;
            f = fn;
        }
    }

    // Block reduction -> per-block partial
#pragma unroll
    for (int o = 16; o > 0; o >>= 1)
        ssum += __shfl_xor_sync(0xFFFFFFFFu, ssum, o);
    int lane = tid & 31;
    int wid  = tid >> 5;
    if (lane == 0) warp_sums[wid] = ssum;
    __syncthreads();

    __shared__ bool is_last;
    if (tid == 0) {
        float bs = 0.0f;
#pragma unroll
        for (int w = 0; w < TPB / 32; w++) bs += warp_sums[w];
        g_partials[blockIdx.x] = bs;
        __threadfence();
        int prev = atomicAdd(&g_count, 1);
        is_last = (prev == gridDim.x - 1);
    }
    __syncthreads();

    // Last block: reduce all partials in double, write scalar, reset counter.
    if (is_last) {
        double acc = 0.0;
        for (int i = tid; i < gridDim.x; i += TPB)
            acc += (double)g_partials[i];
#pragma unroll
        for (int o = 16; o > 0; o >>= 1)
            acc += __shfl_xor_sync(0xFFFFFFFFu, acc, o);
        __shared__ double wsd[TPB / 32];
        if (lane == 0) wsd[wid] = acc;
        __syncthreads();
        if (tid == 0) {
            double tot = 0.0;
#pragma unroll
            for (int w = 0; w < TPB / 32; w++) tot += wsd[w];
            out[0] = (float)tot;
            g_count = 0;   // self-reset for next graph replay
        }
    }
}

extern "C" void kernel_launch(void* const* d_in, const int* in_sizes, int n_in,
                              void* d_out, int out_size) {
    const float* y0 = (const float*)d_in[0];
    const float* W1 = (const float*)d_in[1];
    const float* b1 = (const float*)d_in[2];
    const float* W2 = (const float*)d_in[3];
    const float* b2 = (const float*)d_in[4];
    const float* t1 = (const float*)d_in[5];
    float* out = (float*)d_out;

    int B = in_sizes[0] / 4;
    int blocks = (B + TPB - 1) / TPB;   // 1024 for B=131072

    ode_kernel<<<blocks, TPB>>>(reinterpret_cast<const float4*>(y0),
                                W1, b1, W2, b2, t1, out, B);
}